// round 7
// baseline (speedup 1.0000x reference)
#include <cuda_runtime.h>
#include <math.h>

// Problem dims: x [8, 512, 64, 64]
#define NB 8
#define NC 512
#define SP 4096              // 64*64
#define TOTAL (NB*NC*SP)     // 16,777,216

// ---------------- device scratch (no allocation allowed) ----------------
__device__ float g_A[64*64];        // 64-pt DCT matrix A[k][n]
__device__ float g_AT[64*64];       // transpose
__device__ float g_Ak[512*512];     // 512-pt DCT
__device__ float g_AkT[512*512];
__device__ float g_G[4*128*512];    // G_j = W1_j @ Ak^T
__device__ float g_t[TOTAL];        // forward 2D-DCT result / scratch
__device__ float g_D[TOTAL];        // full 3D DCT coefficients
__device__ float g_logits[TOTAL];   // concatenated branch outputs
__device__ float g_u[NB*128*SP];
__device__ float g_v[NB*128*SP];
__device__ float g_W2r[4*9*128*128];
__device__ unsigned int g_hist1[4096];
__device__ unsigned int g_hist2[4*4096];
__device__ unsigned int g_hist3[4*128];
__device__ unsigned int g_selb1[4], g_selb2[4];
__device__ unsigned int g_selr1[4], g_selr2[4];
__device__ float g_thr[4];

// ---------------- DCT basis construction (mimic fp32 reference exactly) ----------------
__global__ void init_mats() {
    int idx = blockIdx.x * blockDim.x + threadIdx.x;
    if (idx < 64*64) {
        int k = idx >> 6, n = idx & 63;
        float prod = (float)k * ((float)n + 0.5f);
        float arg  = prod * (float)(M_PI / 64.0);
        float v = cosf(arg) * (float)sqrt(2.0/64.0);
        if (k == 0) v = v / (float)sqrt(2.0);
        g_A [k*64 + n] = v;
        g_AT[n*64 + k] = v;
    }
    if (idx < 512*512) {
        int k = idx >> 9, c = idx & 511;
        float prod = (float)k * ((float)c + 0.5f);
        float arg  = prod * (float)(M_PI / 512.0);
        float v = cosf(arg) * (float)sqrt(2.0/512.0);
        if (k == 0) v = v / (float)sqrt(2.0);
        g_Ak [k*512 + c] = v;
        g_AkT[c*512 + k] = v;
    }
}

// Reorder W2 [4][o=128][i=128][3][3] -> [4][tap=9][i=128][o=128]
__global__ void reorder_w2(const float* __restrict__ W2) {
    int idx = blockIdx.x * blockDim.x + threadIdx.x;
    if (idx >= 4*9*128*128) return;
    int o  = idx & 127;
    int ci = (idx >> 7) & 127;
    int t  = (idx >> 14) % 9;
    int j  = (idx >> 14) / 9;
    g_W2r[idx] = W2[((size_t)(j*128 + o)*128 + ci)*9 + t];
}

__global__ void zero_hists() {
    int i = blockIdx.x * blockDim.x + threadIdx.x;
    if (i < 4096)   g_hist1[i] = 0;
    if (i < 4*4096) g_hist2[i] = 0;
    if (i < 4*128)  g_hist3[i] = 0;
}

// ---------------- per-slice 2D transform: OUT = L @ (S @ Rt) ----------------
// forward: L=A, Rt=A^T  (N-transform then M-transform)
// inverse: L=A^T, Rt=A  (N-inverse then M-inverse) ; optional bias+relu epilogue
__global__ __launch_bounds__(256) void slice2d(
    const float* __restrict__ in, float* __restrict__ out,
    const float* __restrict__ L, const float* __restrict__ Rt,
    const float* __restrict__ bias, int nch)
{
    __shared__ __align__(16) float S[64][68];
    __shared__ __align__(16) float Msm[64][64];
    int tid = threadIdx.x;
    const float* src = in + (size_t)blockIdx.x * 4096;

    for (int i = tid; i < 4096; i += 256) S[i >> 6][i & 63] = src[i];
    for (int i = tid; i < 4096; i += 256) Msm[i >> 6][i & 63] = Rt[i];
    __syncthreads();

    int tr = tid >> 4, tc = tid & 15;   // 16x16 thread grid, each thread 4x4
    float t1[4][4] = {};
    #pragma unroll 4
    for (int n = 0; n < 64; n++) {
        float4 r4 = *(const float4*)&Msm[n][tc*4];
        float rv[4] = {r4.x, r4.y, r4.z, r4.w};
        #pragma unroll
        for (int i = 0; i < 4; i++) {
            float s = S[tr*4 + i][n];
            #pragma unroll
            for (int jj = 0; jj < 4; jj++) t1[i][jj] += s * rv[jj];
        }
    }
    __syncthreads();
    #pragma unroll
    for (int i = 0; i < 4; i++)
        #pragma unroll
        for (int jj = 0; jj < 4; jj++) S[tr*4 + i][tc*4 + jj] = t1[i][jj];
    for (int i = tid; i < 4096; i += 256) Msm[i >> 6][i & 63] = L[i];
    __syncthreads();

    float o[4][4] = {};
    #pragma unroll 4
    for (int m = 0; m < 64; m++) {
        float4 t4 = *(const float4*)&S[m][tc*4];
        float tv[4] = {t4.x, t4.y, t4.z, t4.w};
        #pragma unroll
        for (int i = 0; i < 4; i++) {
            float lv = Msm[tr*4 + i][m];
            #pragma unroll
            for (int jj = 0; jj < 4; jj++) o[i][jj] += lv * tv[jj];
        }
    }
    float* dst = out + (size_t)blockIdx.x * 4096;
    bool dorelu = (bias != nullptr);
    float bi = dorelu ? bias[blockIdx.x % nch] : 0.f;
    #pragma unroll
    for (int i = 0; i < 4; i++) {
        float4 v;
        v.x = o[i][0]; v.y = o[i][1]; v.z = o[i][2]; v.w = o[i][3];
        if (dorelu) {
            v.x = fmaxf(v.x + bi, 0.f); v.y = fmaxf(v.y + bi, 0.f);
            v.z = fmaxf(v.z + bi, 0.f); v.w = fmaxf(v.w + bi, 0.f);
        }
        *(float4*)&dst[(tr*4 + i)*64 + tc*4] = v;
    }
}

// ---------------- generic tiled SGEMM: C = A(MxK) @ B(KxN), row-major ----------------
// MASK: zero B elements with |v| < g_thr[thrIdx].  BIASRELU: C = relu(C + bias[m]).
template<bool MASK, bool BIASRELU>
__global__ __launch_bounds__(256) void gemm_k(
    const float* __restrict__ A, const float* __restrict__ B, float* __restrict__ C,
    int M, int N, int K, int ldc,
    long long aBatch, long long bBatch, long long cBatch,
    const float* __restrict__ bias, int thrIdx)
{
    A += (size_t)blockIdx.z * aBatch;
    B += (size_t)blockIdx.z * bBatch;
    C += (size_t)blockIdx.z * cBatch;
    const int m0 = blockIdx.y * 64;
    const int n0 = blockIdx.x * 64;
    float thr = 0.f;
    if (MASK) thr = g_thr[thrIdx];

    __shared__ __align__(16) float As[16][68];
    __shared__ __align__(16) float Bs[16][64];
    const int tid = threadIdx.x;
    const int ty = tid >> 4, tx = tid & 15;
    float acc[4][4] = {};

    for (int k0 = 0; k0 < K; k0 += 16) {
        #pragma unroll
        for (int t = 0; t < 4; t++) {
            int idx = tid + t*256;
            int r = idx >> 4, c = idx & 15;
            As[c][r] = A[(size_t)(m0 + r)*K + (k0 + c)];
        }
        #pragma unroll
        for (int t = 0; t < 4; t++) {
            int idx = tid + t*256;
            int r = idx >> 6, c = idx & 63;
            float v = B[(size_t)(k0 + r)*N + (n0 + c)];
            if (MASK) v = (fabsf(v) >= thr) ? v : 0.f;
            Bs[r][c] = v;
        }
        __syncthreads();
        #pragma unroll
        for (int kk = 0; kk < 16; kk++) {
            float4 a4 = *(const float4*)&As[kk][ty*4];
            float4 b4 = *(const float4*)&Bs[kk][tx*4];
            float av[4] = {a4.x, a4.y, a4.z, a4.w};
            float bv[4] = {b4.x, b4.y, b4.z, b4.w};
            #pragma unroll
            for (int i = 0; i < 4; i++)
                #pragma unroll
                for (int jj = 0; jj < 4; jj++) acc[i][jj] += av[i] * bv[jj];
        }
        __syncthreads();
    }
    #pragma unroll
    for (int i = 0; i < 4; i++) {
        int m = m0 + ty*4 + i;
        float bi = BIASRELU ? bias[m] : 0.f;
        float4 v;
        v.x = acc[i][0]; v.y = acc[i][1]; v.z = acc[i][2]; v.w = acc[i][3];
        if (BIASRELU) {
            v.x = fmaxf(v.x + bi, 0.f); v.y = fmaxf(v.y + bi, 0.f);
            v.z = fmaxf(v.z + bi, 0.f); v.w = fmaxf(v.w + bi, 0.f);
        }
        *(float4*)&C[(size_t)m*ldc + n0 + tx*4] = v;
    }
}

// ---------------- conv2: 3x3, dilation 2, pad 2, 128->128, bias+relu ----------------
// block = (batch, out_row y); computes out[128][64] for that row.
__global__ __launch_bounds__(256) void conv2_dil2(
    const float* __restrict__ in, const float* __restrict__ Wr,
    const float* __restrict__ bias, float* __restrict__ out)
{
    int b = blockIdx.x >> 6;
    int y = blockIdx.x & 63;
    int tid = threadIdx.x;
    int to = tid >> 4;   // out channels to*8 .. to*8+7
    int txx = tid & 15;  // x = txx*4 .. txx*4+3
    __shared__ __align__(16) float Ws[16][128];
    __shared__ float Bsm[16][68];
    float acc[8][4];
    #pragma unroll
    for (int i = 0; i < 8; i++)
        #pragma unroll
        for (int j = 0; j < 4; j++) acc[i][j] = 0.f;

    const float* inb = in + (size_t)b * 128 * 4096;
    for (int ky = 0; ky < 3; ky++) {
        int ry = y + 2*ky - 2;
        if (ry < 0 || ry >= 64) continue;     // uniform per block
        const float* inrow = inb + ry * 64;
        for (int c0 = 0; c0 < 128; c0 += 16) {
            __syncthreads();
            for (int idx = tid; idx < 16*68; idx += 256) {
                int ch = idx / 68, col = idx - ch*68;
                int gx = col - 2;
                Bsm[ch][col] = (gx >= 0 && gx < 64) ? inrow[(size_t)(c0 + ch)*4096 + gx] : 0.f;
            }
            for (int kx = 0; kx < 3; kx++) {
                __syncthreads();
                const float* wp = Wr + ((size_t)(ky*3 + kx)*128 + c0)*128;
                for (int idx = tid; idx < 2048; idx += 256)
                    Ws[idx >> 7][idx & 127] = wp[idx];
                __syncthreads();
                #pragma unroll
                for (int kk = 0; kk < 16; kk++) {
                    float4 w0 = *(const float4*)&Ws[kk][to*8];
                    float4 w1 = *(const float4*)&Ws[kk][to*8 + 4];
                    float wv[8] = {w0.x,w0.y,w0.z,w0.w,w1.x,w1.y,w1.z,w1.w};
                    float bv[4];
                    #pragma unroll
                    for (int j = 0; j < 4; j++) bv[j] = Bsm[kk][txx*4 + j + 2*kx];
                    #pragma unroll
                    for (int i = 0; i < 8; i++)
                        #pragma unroll
                        for (int j = 0; j < 4; j++) acc[i][j] += wv[i] * bv[j];
                }
            }
        }
    }
    float* ob = out + (size_t)b * 128 * 4096 + y * 64;
    #pragma unroll
    for (int i = 0; i < 8; i++) {
        int o = to*8 + i;
        float bi = bias[o];
        float4 v;
        v.x = fmaxf(acc[i][0] + bi, 0.f);
        v.y = fmaxf(acc[i][1] + bi, 0.f);
        v.z = fmaxf(acc[i][2] + bi, 0.f);
        v.w = fmaxf(acc[i][3] + bi, 0.f);
        *(float4*)&ob[(size_t)o*4096 + txx*4] = v;
    }
}

// ---------------- exact top-k thresholds via 3-level radix select on |D| bits ----------------
__global__ void hist_pass1(const float* __restrict__ D) {
    __shared__ unsigned int sh[4096];
    for (int i = threadIdx.x; i < 4096; i += blockDim.x) sh[i] = 0;
    __syncthreads();
    for (int i = blockIdx.x*blockDim.x + threadIdx.x; i < TOTAL; i += gridDim.x*blockDim.x) {
        unsigned int bits = __float_as_uint(fabsf(D[i]));
        atomicAdd(&sh[bits >> 19], 1u);
    }
    __syncthreads();
    for (int i = threadIdx.x; i < 4096; i += blockDim.x)
        if (sh[i]) atomicAdd(&g_hist1[i], sh[i]);
}

__global__ void select_pass1() {
    if (threadIdx.x != 0 || blockIdx.x != 0) return;
    const unsigned int Ks[4] = {TOTAL/4u, TOTAL/16u, TOTAL/64u, TOTAL/256u};
    for (int j = 0; j < 4; j++) {
        unsigned long long cum = 0;
        unsigned int k = Ks[j];
        for (int b = 4095; b >= 0; b--) {
            unsigned int h = g_hist1[b];
            if (cum + h >= (unsigned long long)k) {
                g_selb1[j] = (unsigned int)b;
                g_selr1[j] = (unsigned int)(k - cum);
                break;
            }
            cum += h;
        }
    }
}

__global__ void hist_pass2(const float* __restrict__ D) {
    unsigned int b1[4];
    #pragma unroll
    for (int j = 0; j < 4; j++) b1[j] = g_selb1[j];
    for (int i = blockIdx.x*blockDim.x + threadIdx.x; i < TOTAL; i += gridDim.x*blockDim.x) {
        unsigned int bits = __float_as_uint(fabsf(D[i]));
        unsigned int top = bits >> 19;
        unsigned int mid = (bits >> 7) & 0xFFFu;
        #pragma unroll
        for (int j = 0; j < 4; j++)
            if (top == b1[j]) atomicAdd(&g_hist2[j*4096 + mid], 1u);
    }
}

__global__ void select_pass2() {
    if (threadIdx.x != 0 || blockIdx.x != 0) return;
    for (int j = 0; j < 4; j++) {
        unsigned long long cum = 0;
        unsigned int k = g_selr1[j];
        for (int b = 4095; b >= 0; b--) {
            unsigned int h = g_hist2[j*4096 + b];
            if (cum + h >= (unsigned long long)k) {
                g_selb2[j] = (unsigned int)b;
                g_selr2[j] = (unsigned int)(k - cum);
                break;
            }
            cum += h;
        }
    }
}

__global__ void hist_pass3(const float* __restrict__ D) {
    unsigned int b1[4], b2[4];
    #pragma unroll
    for (int j = 0; j < 4; j++) { b1[j] = g_selb1[j]; b2[j] = g_selb2[j]; }
    for (int i = blockIdx.x*blockDim.x + threadIdx.x; i < TOTAL; i += gridDim.x*blockDim.x) {
        unsigned int bits = __float_as_uint(fabsf(D[i]));
        unsigned int top = bits >> 19;
        unsigned int mid = (bits >> 7) & 0xFFFu;
        unsigned int low = bits & 0x7Fu;
        #pragma unroll
        for (int j = 0; j < 4; j++)
            if (top == b1[j] && mid == b2[j]) atomicAdd(&g_hist3[j*128 + low], 1u);
    }
}

__global__ void select_pass3() {
    if (threadIdx.x != 0 || blockIdx.x != 0) return;
    for (int j = 0; j < 4; j++) {
        unsigned long long cum = 0;
        unsigned int k = g_selr2[j];
        for (int b = 127; b >= 0; b--) {
            unsigned int h = g_hist3[j*128 + b];
            if (cum + h >= (unsigned long long)k) {
                unsigned int bits = (g_selb1[j] << 19) | (g_selb2[j] << 7) | (unsigned int)b;
                g_thr[j] = __uint_as_float(bits);
                break;
            }
            cum += h;
        }
    }
}

// ---------------- softmax over 512 channels + residual ----------------
__global__ void softmax_final(const float* __restrict__ logits, const float* __restrict__ x,
                              float* __restrict__ out)
{
    int p = blockIdx.x*blockDim.x + threadIdx.x;
    if (p >= NB*SP) return;
    int b = p >> 12, mn = p & 4095;
    const float* lg = logits + (size_t)b*NC*SP + mn;
    float mx = -1e30f;
    for (int c = 0; c < NC; c++) mx = fmaxf(mx, lg[(size_t)c*SP]);
    float s = 0.f;
    for (int c = 0; c < NC; c++) s += expf(lg[(size_t)c*SP] - mx);
    float inv = 1.f / s;
    const float* xp = x   + (size_t)b*NC*SP + mn;
    float*       op = out + (size_t)b*NC*SP + mn;
    for (int c = 0; c < NC; c++) {
        float w = expf(lg[(size_t)c*SP] - mx) * inv;
        float xv = xp[(size_t)c*SP];
        op[(size_t)c*SP] = xv * w + xv;
    }
}

// ---------------- launch ----------------
extern "C" void kernel_launch(void* const* d_in, const int* in_sizes, int n_in,
                              void* d_out, int out_size)
{
    const float* x  = (const float*)d_in[0];
    const float* W1 = (const float*)d_in[1];
    const float* b1 = (const float*)d_in[2];
    const float* W2 = (const float*)d_in[3];
    const float* b2 = (const float*)d_in[4];
    const float* W3 = (const float*)d_in[5];
    const float* b3 = (const float*)d_in[6];
    float* out = (float*)d_out;

    float *pA, *pAT, *pAk, *pAkT, *pG, *pt, *pD, *plog, *pu, *pv, *pW2r;
    cudaGetSymbolAddress((void**)&pA,   g_A);
    cudaGetSymbolAddress((void**)&pAT,  g_AT);
    cudaGetSymbolAddress((void**)&pAk,  g_Ak);
    cudaGetSymbolAddress((void**)&pAkT, g_AkT);
    cudaGetSymbolAddress((void**)&pG,   g_G);
    cudaGetSymbolAddress((void**)&pt,   g_t);
    cudaGetSymbolAddress((void**)&pD,   g_D);
    cudaGetSymbolAddress((void**)&plog, g_logits);
    cudaGetSymbolAddress((void**)&pu,   g_u);
    cudaGetSymbolAddress((void**)&pv,   g_v);
    cudaGetSymbolAddress((void**)&pW2r, g_W2r);

    init_mats<<<1024, 256>>>();
    reorder_w2<<<2304, 256>>>(W2);
    zero_hists<<<64, 256>>>();

    // forward 2D DCT per (b,c) slice: t = A @ S @ A^T
    slice2d<<<NB*NC, 256>>>(x, pt, pA, pAT, nullptr, 1);
    // forward C-DCT: D[b] = Ak @ t[b]
    gemm_k<false,false><<<dim3(64, 8, NB), 256>>>(
        pAk, pt, pD, 512, 4096, 512, 4096,
        0LL, (long long)NC*SP, (long long)NC*SP, nullptr, 0);
    // G_j = W1_j @ Ak^T  (fuses invC with conv1)
    gemm_k<false,false><<<dim3(8, 2, 4), 256>>>(
        W1, pAkT, pG, 128, 512, 512, 512,
        (long long)128*512, 0LL, (long long)128*512, nullptr, 0);

    // exact k-th largest |D| thresholds (device-side radix select)
    hist_pass1<<<1024, 256>>>(pD);
    select_pass1<<<1, 32>>>();
    hist_pass2<<<1024, 256>>>(pD);
    select_pass2<<<1, 32>>>();
    hist_pass3<<<1024, 256>>>(pD);
    select_pass3<<<1, 32>>>();

    for (int j = 0; j < 4; j++) {
        // u[b] = G_j @ mask_j(D[b])   (128 x 4096)
        gemm_k<true,false><<<dim3(64, 2, NB), 256>>>(
            pG + (size_t)j*128*512, pD, pu, 128, 4096, 512, 4096,
            0LL, (long long)NC*SP, (long long)128*SP, nullptr, j);
        // spatial inverse per slice + conv1 bias + relu: v = relu(A^T @ U @ A + b1)
        slice2d<<<NB*128, 256>>>(pu, pv, pAT, pA, b1 + j*128, 128);
        // conv2 (3x3 dil 2) + bias + relu: u = conv2(v)
        conv2_dil2<<<NB*64, 256>>>(pv, pW2r + (size_t)j*9*128*128, b2 + j*128, pu);
        // conv3 (1x1) + bias + relu -> logits channel slab j
        gemm_k<false,true><<<dim3(64, 2, NB), 256>>>(
            W3 + (size_t)j*128*128, pu, plog + (size_t)j*128*SP, 128, 4096, 128, 4096,
            0LL, (long long)128*SP, (long long)NC*SP, b3 + j*128, 0);
    }

    softmax_final<<<(NB*SP + 255)/256, 256>>>(plog, x, out);
}

// round 8
// speedup vs baseline: 1.5099x; 1.5099x over previous
#include <cuda_runtime.h>
#include <math.h>

#define NB 8
#define NC 512
#define SP 4096
#define TOTAL (NB*NC*SP)

typedef unsigned long long ull;

__device__ __forceinline__ void ffma2(ull &d, ull a, ull b) {
    asm("fma.rn.f32x2 %0, %1, %2, %0;" : "+l"(d) : "l"(a), "l"(b));
}
__device__ __forceinline__ ull pack2(float lo, float hi) {
    ull r; asm("mov.b64 %0, {%1, %2};" : "=l"(r) : "f"(lo), "f"(hi)); return r;
}
__device__ __forceinline__ void unpack2(ull v, float &lo, float &hi) {
    asm("mov.b64 {%0, %1}, %2;" : "=f"(lo), "=f"(hi) : "l"(v));
}

// ---------------- device scratch ----------------
__device__ float g_A[64*64];
__device__ float g_AT[64*64];
__device__ float g_Ak[512*512];
__device__ float g_AkT[512*512];
__device__ float g_G[4*128*512];
__device__ float g_t[TOTAL];
__device__ float g_D[TOTAL];
__device__ float g_logits[TOTAL];
__device__ float g_u[4*NB*128*SP];
__device__ float g_v[4*NB*128*SP];
__device__ float g_W2c[4*128*1152];     // [j][o][tap*128+i]
__device__ unsigned int g_hist1[4096];
__device__ unsigned int g_hist2[4*4096];
__device__ unsigned int g_hist3[4*128];
__device__ unsigned int g_selb1[4], g_selb2[4];
__device__ unsigned int g_selr1[4], g_selr2[4];
__device__ float g_thr[4];

// ---------------- init ----------------
__global__ void init_mats() {
    int idx = blockIdx.x * blockDim.x + threadIdx.x;
    if (idx < 64*64) {
        int k = idx >> 6, n = idx & 63;
        float v = cosf((float)k * ((float)n + 0.5f) * (float)(M_PI / 64.0)) * (float)sqrt(2.0/64.0);
        if (k == 0) v = v / (float)sqrt(2.0);
        g_A [k*64 + n] = v;
        g_AT[n*64 + k] = v;
    }
    if (idx < 512*512) {
        int k = idx >> 9, c = idx & 511;
        float v = cosf((float)k * ((float)c + 0.5f) * (float)(M_PI / 512.0)) * (float)sqrt(2.0/512.0);
        if (k == 0) v = v / (float)sqrt(2.0);
        g_Ak [k*512 + c] = v;
        g_AkT[c*512 + k] = v;
    }
}

// W2 [4][o=128][i=128][3][3] -> [4][o=128][tap=9][i=128]
__global__ void reorder_w2(const float* __restrict__ W2) {
    int idx = blockIdx.x * blockDim.x + threadIdx.x;
    if (idx >= 4*128*9*128) return;
    int i   = idx & 127;
    int t2  = idx >> 7;
    int tap = t2 % 9;
    int t3  = t2 / 9;
    int o   = t3 & 127;
    int j   = t3 >> 7;
    g_W2c[idx] = W2[((size_t)((j*128 + o)*128 + i))*9 + tap];
}

__global__ void zero_hists() {
    int i = blockIdx.x * blockDim.x + threadIdx.x;
    if (i < 4096)   g_hist1[i] = 0;
    if (i < 4*4096) g_hist2[i] = 0;
    if (i < 4*128)  g_hist3[i] = 0;
}

// ---------------- per-slice 2D transform: OUT = L @ (S @ Rt), f32x2 ----------------
// biasMode 0: none. 1: bias[((blk>>10)<<7) | (blk&127)], relu.
__global__ __launch_bounds__(256) void slice2d(
    const float* __restrict__ in, float* __restrict__ out,
    const float* __restrict__ L, const float* __restrict__ Rt,
    const float* __restrict__ bias, int biasMode)
{
    __shared__ __align__(16) float S[64][68];
    __shared__ __align__(16) float Msm[64][64];
    int tid = threadIdx.x;
    const float* src = in + (size_t)blockIdx.x * 4096;

    for (int i = tid; i < 4096; i += 256) S[i >> 6][i & 63] = src[i];
    for (int i = tid; i < 4096; i += 256) Msm[i >> 6][i & 63] = Rt[i];
    __syncthreads();

    int tr = tid >> 4, tc = tid & 15;
    ull t1[4][2] = {};
    #pragma unroll 4
    for (int n = 0; n < 64; n++) {
        ull b0 = *(const ull*)&Msm[n][tc*4];
        ull b1 = *(const ull*)&Msm[n][tc*4 + 2];
        #pragma unroll
        for (int i = 0; i < 4; i++) {
            float s = S[tr*4 + i][n];
            ull sp = pack2(s, s);
            ffma2(t1[i][0], sp, b0);
            ffma2(t1[i][1], sp, b1);
        }
    }
    __syncthreads();
    #pragma unroll
    for (int i = 0; i < 4; i++) {
        *(ull*)&S[tr*4 + i][tc*4]     = t1[i][0];
        *(ull*)&S[tr*4 + i][tc*4 + 2] = t1[i][1];
    }
    for (int i = tid; i < 4096; i += 256) Msm[i >> 6][i & 63] = L[i];
    __syncthreads();

    ull o2[4][2] = {};
    #pragma unroll 4
    for (int m = 0; m < 64; m++) {
        ull b0 = *(const ull*)&S[m][tc*4];
        ull b1 = *(const ull*)&S[m][tc*4 + 2];
        #pragma unroll
        for (int i = 0; i < 4; i++) {
            float lv = Msm[tr*4 + i][m];
            ull lp = pack2(lv, lv);
            ffma2(o2[i][0], lp, b0);
            ffma2(o2[i][1], lp, b1);
        }
    }
    float* dst = out + (size_t)blockIdx.x * 4096;
    float bi = 0.f;
    if (biasMode) bi = bias[(((unsigned)blockIdx.x >> 10) << 7) | (blockIdx.x & 127)];
    #pragma unroll
    for (int i = 0; i < 4; i++) {
        float4 v;
        unpack2(o2[i][0], v.x, v.y);
        unpack2(o2[i][1], v.z, v.w);
        if (biasMode) {
            v.x = fmaxf(v.x + bi, 0.f); v.y = fmaxf(v.y + bi, 0.f);
            v.z = fmaxf(v.z + bi, 0.f); v.w = fmaxf(v.w + bi, 0.f);
        }
        *(float4*)&dst[(tr*4 + i)*64 + tc*4] = v;
    }
}

// ---------------- 128x128-tile f32x2 SGEMM ----------------
// C = A(MxK) @ B(KxN) row-major, ldc=N. jj = z/zDiv (branch), bb = z%zDiv (batch).
// MASK: zero B where |v| < g_thr[jj]. BIASRELU: relu(C + bias[jj*biasJ + m]).
// CONV: B index is dilated-2 3x3 shift of in[i] (K = 9*128, k = tap*128 + i).
template<bool MASK, bool BIASRELU, bool CONV>
__global__ __launch_bounds__(256) void gemm128(
    const float* __restrict__ A, const float* __restrict__ B, float* __restrict__ C,
    int N, int K, int zDiv,
    long long aJ, long long aB, long long bJ, long long bB,
    long long cJ, long long cB,
    const float* __restrict__ bias, int biasJ)
{
    const int jj = blockIdx.z / zDiv, bb = blockIdx.z % zDiv;
    A += jj*aJ + (long long)bb*aB;
    B += jj*bJ + (long long)bb*bB;
    C += jj*cJ + (long long)bb*cB;
    const int m0 = blockIdx.y * 128;
    const int n0 = blockIdx.x * 128;
    float thr = 0.f;
    if (MASK) thr = g_thr[jj];

    __shared__ __align__(16) float As[16][132];   // [k][m]
    __shared__ __align__(16) float Bs[16][128];   // [k][n]
    const int tid = threadIdx.x;
    const int tr = tid >> 5;      // warp id: rows tr*16..tr*16+15
    const int tc = tid & 31;      // cols tc + 32u

    ull acc[8][4];
    #pragma unroll
    for (int p = 0; p < 8; p++)
        #pragma unroll
        for (int u = 0; u < 4; u++) acc[p][u] = 0ull;

    for (int k0 = 0; k0 < K; k0 += 16) {
        #pragma unroll
        for (int t = 0; t < 8; t++) {
            int idx = tid + t*256;
            int r = idx >> 4, c = idx & 15;
            As[c][r] = A[(size_t)(m0 + r)*K + (k0 + c)];
        }
        #pragma unroll
        for (int t = 0; t < 8; t++) {
            int idx = tid + t*256;
            int r = idx >> 7, c = idx & 127;
            float v;
            if (CONV) {
                int kg = k0 + r;
                int tap = kg >> 7, ci = kg & 127;
                int dy = 2*(tap/3) - 2, dx = 2*(tap%3) - 2;
                int n = n0 + c;
                int gy = (n >> 6) + dy, gx = (n & 63) + dx;
                v = ((unsigned)gy < 64u && (unsigned)gx < 64u)
                    ? B[(size_t)ci*4096 + gy*64 + gx] : 0.f;
            } else {
                v = B[(size_t)(k0 + r)*N + (n0 + c)];
                if (MASK) v = (fabsf(v) >= thr) ? v : 0.f;
            }
            Bs[r][c] = v;
        }
        __syncthreads();
        #pragma unroll
        for (int kk = 0; kk < 16; kk++) {
            const ull* ap = (const ull*)&As[kk][tr*16];
            ull a[8];
            #pragma unroll
            for (int p = 0; p < 8; p++) a[p] = ap[p];
            ull b2[4];
            #pragma unroll
            for (int u = 0; u < 4; u++) {
                float bv = Bs[kk][tc + 32*u];
                b2[u] = pack2(bv, bv);
            }
            #pragma unroll
            for (int p = 0; p < 8; p++)
                #pragma unroll
                for (int u = 0; u < 4; u++)
                    ffma2(acc[p][u], a[p], b2[u]);
        }
        __syncthreads();
    }
    #pragma unroll
    for (int p = 0; p < 8; p++) {
        int mlo = m0 + tr*16 + 2*p;
        float blo = 0.f, bhi = 0.f;
        if (BIASRELU) { blo = bias[jj*biasJ + mlo]; bhi = bias[jj*biasJ + mlo + 1]; }
        #pragma unroll
        for (int u = 0; u < 4; u++) {
            float lo, hi; unpack2(acc[p][u], lo, hi);
            int col = n0 + tc + 32*u;
            if (BIASRELU) { lo = fmaxf(lo + blo, 0.f); hi = fmaxf(hi + bhi, 0.f); }
            C[(size_t)mlo*N + col]       = lo;
            C[(size_t)(mlo + 1)*N + col] = hi;
        }
    }
}

// ---------------- histograms (3-level radix on |D| bit patterns) ----------------
__global__ void hist_pass1(const float* __restrict__ D) {
    __shared__ unsigned int sh[4096];
    for (int i = threadIdx.x; i < 4096; i += blockDim.x) sh[i] = 0;
    __syncthreads();
    for (int i = blockIdx.x*blockDim.x + threadIdx.x; i < TOTAL; i += gridDim.x*blockDim.x)
        atomicAdd(&sh[__float_as_uint(fabsf(D[i])) >> 19], 1u);
    __syncthreads();
    for (int i = threadIdx.x; i < 4096; i += blockDim.x)
        if (sh[i]) atomicAdd(&g_hist1[i], sh[i]);
}

__global__ void hist_pass2(const float* __restrict__ D) {
    unsigned int b1[4];
    #pragma unroll
    for (int j = 0; j < 4; j++) b1[j] = g_selb1[j];
    for (int i = blockIdx.x*blockDim.x + threadIdx.x; i < TOTAL; i += gridDim.x*blockDim.x) {
        unsigned int bits = __float_as_uint(fabsf(D[i]));
        unsigned int top = bits >> 19, mid = (bits >> 7) & 0xFFFu;
        #pragma unroll
        for (int j = 0; j < 4; j++)
            if (top == b1[j]) atomicAdd(&g_hist2[j*4096 + mid], 1u);
    }
}

__global__ void hist_pass3(const float* __restrict__ D) {
    unsigned int b1[4], b2[4];
    #pragma unroll
    for (int j = 0; j < 4; j++) { b1[j] = g_selb1[j]; b2[j] = g_selb2[j]; }
    for (int i = blockIdx.x*blockDim.x + threadIdx.x; i < TOTAL; i += gridDim.x*blockDim.x) {
        unsigned int bits = __float_as_uint(fabsf(D[i]));
        unsigned int top = bits >> 19, mid = (bits >> 7) & 0xFFFu, low = bits & 0x7Fu;
        #pragma unroll
        for (int j = 0; j < 4; j++)
            if (top == b1[j] && mid == b2[j]) atomicAdd(&g_hist3[j*128 + low], 1u);
    }
}

// ---------------- warp-parallel descending select ----------------
// Finds (bin, remaining) s.t. walking bins descending, first bin where cum+h >= k.
__device__ __forceinline__ void warp_select(
    const unsigned int* hist, int nbins, unsigned int k, int lane,
    unsigned int &outb, unsigned int &outr)
{
    const int bpl = nbins >> 5;
    unsigned int s = 0;
    for (int i = 0; i < bpl; i++) s += hist[lane*bpl + i];
    unsigned int suf = s;   // inclusive suffix: sum over lanes >= lane
    #pragma unroll
    for (int d = 1; d < 32; d <<= 1) {
        unsigned int t = __shfl_down_sync(0xffffffffu, suf, d);
        if (lane + d < 32) suf += t;
    }
    unsigned int bfound = 0xffffffffu, rfound = 0;
    if (suf >= k && suf - s < k) {       // k-th element lives in this lane's chunk
        unsigned int cum = suf - s;
        for (int b = lane*bpl + bpl - 1; b >= lane*bpl; b--) {
            unsigned int h = hist[b];
            if (cum + h >= k) { bfound = (unsigned int)b; rfound = k - cum; break; }
            cum += h;
        }
    }
    unsigned int mask = __ballot_sync(0xffffffffu, bfound != 0xffffffffu);
    int src = __ffs(mask) - 1;
    outb = __shfl_sync(0xffffffffu, bfound, src);
    outr = __shfl_sync(0xffffffffu, rfound, src);
}

__global__ void select_all(int pass) {
    int j = threadIdx.x >> 5, lane = threadIdx.x & 31;
    if (j >= 4) return;
    unsigned int b, r;
    if (pass == 1) {
        const unsigned int Ks[4] = {TOTAL/4u, TOTAL/16u, TOTAL/64u, TOTAL/256u};
        warp_select(g_hist1, 4096, Ks[j], lane, b, r);
        if (lane == 0) { g_selb1[j] = b; g_selr1[j] = r; }
    } else if (pass == 2) {
        warp_select(g_hist2 + j*4096, 4096, g_selr1[j], lane, b, r);
        if (lane == 0) { g_selb2[j] = b; g_selr2[j] = r; }
    } else {
        warp_select(g_hist3 + j*128, 128, g_selr2[j], lane, b, r);
        if (lane == 0) {
            unsigned int bits = (g_selb1[j] << 19) | (g_selb2[j] << 7) | b;
            g_thr[j] = __uint_as_float(bits);
        }
    }
}

// ---------------- softmax over 512 channels + residual ----------------
__global__ void softmax_final(const float* __restrict__ logits, const float* __restrict__ x,
                              float* __restrict__ out)
{
    int p = blockIdx.x*blockDim.x + threadIdx.x;
    if (p >= NB*SP) return;
    int b = p >> 12, mn = p & 4095;
    const float* lg = logits + (size_t)b*NC*SP + mn;
    float mx = -1e30f;
    for (int c = 0; c < NC; c++) mx = fmaxf(mx, lg[(size_t)c*SP]);
    float s = 0.f;
    for (int c = 0; c < NC; c++) s += expf(lg[(size_t)c*SP] - mx);
    float inv = 1.f / s;
    const float* xp = x   + (size_t)b*NC*SP + mn;
    float*       op = out + (size_t)b*NC*SP + mn;
    for (int c = 0; c < NC; c++) {
        float w = expf(lg[(size_t)c*SP] - mx) * inv;
        float xv = xp[(size_t)c*SP];
        op[(size_t)c*SP] = xv * w + xv;
    }
}

// ---------------- launch ----------------
extern "C" void kernel_launch(void* const* d_in, const int* in_sizes, int n_in,
                              void* d_out, int out_size)
{
    const float* x  = (const float*)d_in[0];
    const float* W1 = (const float*)d_in[1];
    const float* b1 = (const float*)d_in[2];
    const float* W2 = (const float*)d_in[3];
    const float* b2 = (const float*)d_in[4];
    const float* W3 = (const float*)d_in[5];
    const float* b3 = (const float*)d_in[6];
    float* out = (float*)d_out;

    float *pA, *pAT, *pAk, *pAkT, *pG, *pt, *pD, *plog, *pu, *pv, *pW2c;
    cudaGetSymbolAddress((void**)&pA,   g_A);
    cudaGetSymbolAddress((void**)&pAT,  g_AT);
    cudaGetSymbolAddress((void**)&pAk,  g_Ak);
    cudaGetSymbolAddress((void**)&pAkT, g_AkT);
    cudaGetSymbolAddress((void**)&pG,   g_G);
    cudaGetSymbolAddress((void**)&pt,   g_t);
    cudaGetSymbolAddress((void**)&pD,   g_D);
    cudaGetSymbolAddress((void**)&plog, g_logits);
    cudaGetSymbolAddress((void**)&pu,   g_u);
    cudaGetSymbolAddress((void**)&pv,   g_v);
    cudaGetSymbolAddress((void**)&pW2c, g_W2c);

    const long long BSLAB = (long long)128*SP;      // per-branch-per-batch slab
    const long long JSLAB = (long long)NB*128*SP;   // per-branch slab in u/v

    init_mats<<<1024, 256>>>();
    reorder_w2<<<2304, 256>>>(W2);
    zero_hists<<<64, 256>>>();

    // forward 2D DCT per (b,c) slice: t = A @ S @ A^T
    slice2d<<<NB*NC, 256>>>(x, pt, pA, pAT, nullptr, 0);
    // forward C-DCT: D[b] = Ak @ t[b]   (M=512 -> 4 y-tiles)
    gemm128<false,false,false><<<dim3(32, 4, 8), 256>>>(
        pAk, pt, pD, 4096, 512, 8,
        0LL, 0LL, 0LL, (long long)NC*SP, 0LL, (long long)NC*SP, nullptr, 0);
    // G_j = W1_j @ Ak^T
    gemm128<false,false,false><<<dim3(4, 1, 4), 256>>>(
        W1, pAkT, pG, 512, 512, 1,
        (long long)128*512, 0LL, 0LL, 0LL, (long long)128*512, 0LL, nullptr, 0);

    // exact k-th largest |D| thresholds
    hist_pass1<<<1024, 256>>>(pD);
    select_all<<<1, 128>>>(1);
    hist_pass2<<<1024, 256>>>(pD);
    select_all<<<1, 128>>>(2);
    hist_pass3<<<1024, 256>>>(pD);
    select_all<<<1, 128>>>(3);

    // u[j][b] = G_j @ mask_j(D[b])   — all branches+batches in one launch
    gemm128<true,false,false><<<dim3(32, 1, 32), 256>>>(
        pG, pD, pu, 4096, 512, 8,
        (long long)128*512, 0LL, 0LL, (long long)NC*SP, JSLAB, BSLAB, nullptr, 0);
    // spatial inverse + conv1 bias + relu: v = relu(A^T @ U @ A + b1[j])
    slice2d<<<4*NB*128, 256>>>(pu, pv, pAT, pA, b1, 1);
    // conv2 (3x3 dil2, shifted-B GEMM over K=1152) + bias + relu: u = conv2(v)
    gemm128<false,true,true><<<dim3(32, 1, 32), 256>>>(
        pW2c, pv, pu, 4096, 1152, 8,
        (long long)128*1152, 0LL, JSLAB, BSLAB, JSLAB, BSLAB, b2, 128);
    // conv3 (1x1) + bias + relu -> logits slab j
    gemm128<false,true,false><<<dim3(32, 1, 32), 256>>>(
        W3, pu, plog, 4096, 128, 8,
        (long long)128*128, 0LL, JSLAB, BSLAB, (long long)128*SP, (long long)NC*SP, b3, 128);

    softmax_final<<<(NB*SP + 255)/256, 256>>>(plog, x, out);
}